// round 8
// baseline (speedup 1.0000x reference)
#include <cuda_runtime.h>
#include <cuda_fp16.h>
#include <cstdint>

// ---------------------------------------------------------------------------
// WindowAttention (reference semantics):
//   qkv = window_gather(x) @ w_qkv^T          [100352 x 768]
//   per token: A[h,e] = softmax_e(q_h . k_e / sqrt(32));  o_h = sum_e A[h,e] v_e
//   att layout per window: h*1568 + s*32 + d  (swapaxes(1,2) flatten)
//   out = att @ w_proj^T + b, window-scattered back to (32,56,56,256)
//
// GEMMs: fp16 mma.sync.m16n8k16 (fp32 accumulate). fp16 carries the same 11
// mantissa bits as tf32 (measured 4.2e-4) but 2x K per instruction, half the
// smem, and ldmatrix.x4 fragment loads.
// ---------------------------------------------------------------------------

#define M_TOK 100352
#define KDIM  256
#define QKV_N 768

__device__ float g_qkv[(size_t)M_TOK * QKV_N];
__device__ float g_att[(size_t)M_TOK * KDIM];

__device__ __forceinline__ int row_offset(int n) {
    int w  = n / 49;
    int s  = n - w * 49;
    int b  = w >> 6;
    int wh = (w >> 3) & 7;
    int ww = w & 7;
    int r  = s / 7;
    int cc = s - r * 7;
    int hh = wh * 7 + r;
    int wc = ww * 7 + cc;
    return ((b * 56 + hh) * 56 + wc) * 256;
}

// ---------------------------------------------------------------------------
// fp16 TC GEMM: C[M x NTOT] = A[M x 256] * B[NTOT x 256]^T
// Tile 64x128, BK=64 halves (128B rows, SW128 swizzle), 256 thr,
// 8 warps x (32x32), register-prefetch of next K-chunk.
// ---------------------------------------------------------------------------
#define BM 64
#define BN 128

__device__ __forceinline__ uint32_t pk(float x, float y) {
    __half2 h = __floats2half2_rn(x, y);   // .x = low = x
    return *reinterpret_cast<uint32_t*>(&h);
}
__device__ __forceinline__ void ldm4(uint32_t r[4], uint32_t a) {
    asm volatile("ldmatrix.sync.aligned.m8n8.x4.shared.b16 {%0,%1,%2,%3}, [%4];"
        : "=r"(r[0]), "=r"(r[1]), "=r"(r[2]), "=r"(r[3]) : "r"(a));
}
__device__ __forceinline__ void mma16816(float c[4], const uint32_t a[4],
                                         uint32_t b0, uint32_t b1) {
    asm volatile(
        "mma.sync.aligned.m16n8k16.row.col.f32.f16.f16.f32 "
        "{%0,%1,%2,%3}, {%4,%5,%6,%7}, {%8,%9}, {%0,%1,%2,%3};"
        : "+f"(c[0]), "+f"(c[1]), "+f"(c[2]), "+f"(c[3])
        : "r"(a[0]), "r"(a[1]), "r"(a[2]), "r"(a[3]), "r"(b0), "r"(b1));
}

template<int NTOT, bool GATHER_A, bool SCATTER_OUT>
__global__ __launch_bounds__(256, 2)
void gemm_f16(const float* __restrict__ A, const float* __restrict__ B,
              const float* __restrict__ bias, float* __restrict__ Cout)
{
    __shared__ __align__(128) char smA[BM * 128];   // 8KB : 64 rows x 64 halves
    __shared__ __align__(128) char smB[BN * 128];   // 16KB: 128 rows x 64 halves

    const int tid  = threadIdx.x;
    const int lane = tid & 31;
    const int warp = tid >> 5;
    const int g = lane >> 2;
    const int q = lane & 3;
    const int wm = (warp & 1) * 32;
    const int wn = (warp >> 1) * 32;

    const int m0 = blockIdx.y * BM;
    const int n0 = blockIdx.x * BN;

    const uint32_t sA = (uint32_t)__cvta_generic_to_shared(smA);
    const uint32_t sB = (uint32_t)__cvta_generic_to_shared(smB);

    // loader geometry
    const int ar  = tid >> 2;             // A row 0..63
    const int acb = (tid & 3) * 16;       // A col base (16 fp32)
    const int br  = tid >> 1;             // B row 0..127
    const int bcb = (tid & 1) * 32;       // B col base (32 fp32)
    const long abase = (GATHER_A ? (long)row_offset(m0 + ar)
                                 : (long)(m0 + ar) * KDIM) + acb;
    const long bbase = (long)(n0 + br) * KDIM + bcb;
    const uint32_t aswz = (uint32_t)(ar & 7) << 4;
    const uint32_t bswz = (uint32_t)(br & 7) << 4;

    // fragment lane geometry (SW128: col ^ ((row&7)<<4))
    const int a_r   = lane & 15;
    const uint32_t a_c   = lane & 16;
    const uint32_t a_swz = (uint32_t)(a_r & 7) << 4;
    const uint32_t a_base = sA + (uint32_t)(wm + a_r) * 128;
    const int b_r   = (lane & 7) + ((lane & 16) >> 1);
    const uint32_t b_c   = (lane & 8) << 1;
    const uint32_t b_swz = (uint32_t)(b_r & 7) << 4;
    const uint32_t b_base = sB + (uint32_t)(wn + b_r) * 128;

    float acc[2][4][4];
    #pragma unroll
    for (int i = 0; i < 2; i++)
        #pragma unroll
        for (int j = 0; j < 4; j++)
            #pragma unroll
            for (int c = 0; c < 4; c++) acc[i][j][c] = 0.f;

    float4 pa[4], pb[8];
    auto ldchunk = [&](int kc) {
        const float* ga = A + abase + kc;
        const float* gb = B + bbase + kc;
        #pragma unroll
        for (int i = 0; i < 4; i++) pa[i] = *(const float4*)(ga + i * 4);
        #pragma unroll
        for (int i = 0; i < 8; i++) pb[i] = *(const float4*)(gb + i * 4);
    };
    auto stchunk = [&]() {
        #pragma unroll
        for (int i = 0; i < 2; i++) {
            uint4 u;
            u.x = pk(pa[2*i].x,   pa[2*i].y);
            u.y = pk(pa[2*i].z,   pa[2*i].w);
            u.z = pk(pa[2*i+1].x, pa[2*i+1].y);
            u.w = pk(pa[2*i+1].z, pa[2*i+1].w);
            uint32_t off = (uint32_t)(ar * 128) + (((uint32_t)(acb * 2 + i * 16)) ^ aswz);
            *(uint4*)(smA + off) = u;
        }
        #pragma unroll
        for (int i = 0; i < 4; i++) {
            uint4 u;
            u.x = pk(pb[2*i].x,   pb[2*i].y);
            u.y = pk(pb[2*i].z,   pb[2*i].w);
            u.z = pk(pb[2*i+1].x, pb[2*i+1].y);
            u.w = pk(pb[2*i+1].z, pb[2*i+1].w);
            uint32_t off = (uint32_t)(br * 128) + (((uint32_t)(bcb * 2 + i * 16)) ^ bswz);
            *(uint4*)(smB + off) = u;
        }
    };

    ldchunk(0);
    #pragma unroll 1
    for (int c = 0; c < 4; ++c) {
        stchunk();
        __syncthreads();
        if (c < 3) ldchunk((c + 1) * 64);

        #pragma unroll
        for (int ks = 0; ks < 4; ks++) {
            const uint32_t kc32 = (uint32_t)(ks * 32);
            uint32_t af[2][4], bf[2][4];
            #pragma unroll
            for (int mt = 0; mt < 2; mt++)
                ldm4(af[mt], a_base + (uint32_t)(mt * 2048) + ((kc32 + a_c) ^ a_swz));
            #pragma unroll
            for (int p = 0; p < 2; p++)
                ldm4(bf[p], b_base + (uint32_t)(p * 2048) + ((kc32 + b_c) ^ b_swz));
            #pragma unroll
            for (int mt = 0; mt < 2; mt++)
                #pragma unroll
                for (int nt = 0; nt < 4; nt++)
                    mma16816(acc[mt][nt], af[mt], bf[nt >> 1][(nt & 1) * 2],
                             bf[nt >> 1][(nt & 1) * 2 + 1]);
        }
        __syncthreads();
    }

    // epilogue: c0,c1 = (row g, cols 2q,2q+1); c2,c3 = row g+8
    #pragma unroll
    for (int mt = 0; mt < 2; mt++) {
        #pragma unroll
        for (int ri = 0; ri < 2; ri++) {
            const int m = m0 + wm + mt * 16 + g + ri * 8;
            const long ob = SCATTER_OUT ? (long)row_offset(m) : (long)m * NTOT;
            #pragma unroll
            for (int nt = 0; nt < 4; nt++) {
                const int col = n0 + wn + nt * 8 + 2 * q;
                float2 v;
                v.x = acc[mt][nt][ri * 2 + 0];
                v.y = acc[mt][nt][ri * 2 + 1];
                if (SCATTER_OUT) {
                    v.x += bias[col];
                    v.y += bias[col + 1];
                }
                *(float2*)(Cout + ob + col) = v;
            }
        }
    }
}

// ---------------------------------------------------------------------------
// Per-token head-mixing attention (8x8 over heads), fp32.
// ---------------------------------------------------------------------------
#define ATT_TOK 14
#define ATT_THREADS (ATT_TOK * 8)

__global__ __launch_bounds__(ATT_THREADS)
void attn_kernel(const float* __restrict__ qkv, float* __restrict__ att)
{
    __shared__ float rows[ATT_TOK][776];

    const int tid  = threadIdx.x;
    const int tok0 = blockIdx.x * ATT_TOK;

    for (int i = tid; i < ATT_TOK * 192; i += ATT_THREADS) {
        int t = i / 192, c4 = (i - t * 192) * 4;
        *(float4*)&rows[t][c4] =
            *(const float4*)(qkv + (size_t)(tok0 + t) * QKV_N + c4);
    }
    __syncthreads();

    const int t = tid >> 3;
    const int h = tid & 7;
    const float* row = rows[t];

    float qv[32];
    #pragma unroll
    for (int d = 0; d < 32; d++) qv[d] = row[h * 32 + d];

    const float scale = 0.17677669529663687f;
    float a[8];
    #pragma unroll
    for (int e = 0; e < 8; e++) {
        float acc = 0.f;
        #pragma unroll
        for (int d = 0; d < 32; d++) acc += qv[d] * row[256 + e * 32 + d];
        a[e] = acc * scale;
    }

    float mx = a[0];
    #pragma unroll
    for (int e = 1; e < 8; e++) mx = fmaxf(mx, a[e]);
    float sum = 0.f;
    #pragma unroll
    for (int e = 0; e < 8; e++) { a[e] = __expf(a[e] - mx); sum += a[e]; }
    float inv = 1.f / sum;
    #pragma unroll
    for (int e = 0; e < 8; e++) a[e] *= inv;

    const int n = tok0 + t;
    const int w = n / 49;
    const int s = n - w * 49;
    float* op = att + (size_t)w * 12544 + h * 1568 + s * 32;

    #pragma unroll
    for (int d = 0; d < 32; d += 4) {
        float4 o;
        o.x = o.y = o.z = o.w = 0.f;
        #pragma unroll
        for (int e = 0; e < 8; e++) {
            const float* vp = &row[512 + e * 32 + d];
            o.x += a[e] * vp[0];
            o.y += a[e] * vp[1];
            o.z += a[e] * vp[2];
            o.w += a[e] * vp[3];
        }
        *(float4*)(op + d) = o;
    }
}

// ---------------------------------------------------------------------------
extern "C" void kernel_launch(void* const* d_in, const int* in_sizes, int n_in,
                              void* d_out, int out_size)
{
    (void)in_sizes; (void)n_in; (void)out_size;
    const float* x      = (const float*)d_in[0];
    const float* w_qkv  = (const float*)d_in[1];
    const float* w_proj = (const float*)d_in[2];
    const float* b_proj = (const float*)d_in[3];
    float* out = (float*)d_out;

    void* qkv_ptr = nullptr;
    void* att_ptr = nullptr;
    cudaGetSymbolAddress(&qkv_ptr, g_qkv);
    cudaGetSymbolAddress(&att_ptr, g_att);
    float* qkv = (float*)qkv_ptr;
    float* att = (float*)att_ptr;

    {
        dim3 grid(QKV_N / BN, M_TOK / BM);   // (6, 1568)
        gemm_f16<QKV_N, true, false><<<grid, 256>>>(x, w_qkv, nullptr, qkv);
    }
    {
        attn_kernel<<<M_TOK / ATT_TOK, ATT_THREADS>>>(qkv, att);
    }
    {
        dim3 grid(KDIM / BN, M_TOK / BM);    // (2, 1568)
        gemm_f16<KDIM, false, true><<<grid, 256>>>(att, w_proj, b_proj, out);
    }
}

// round 9
// speedup vs baseline: 1.3313x; 1.3313x over previous
#include <cuda_runtime.h>
#include <cuda_fp16.h>
#include <cstdint>

// ---------------------------------------------------------------------------
// WindowAttention (reference semantics):
//   qkv = window_gather(x) @ w_qkv^T          [100352 x 768]
//   per token: A[h,e] = softmax_e(q_h . k_e / sqrt(32));  o_h = sum_e A[h,e] v_e
//   att layout per window: h*1568 + s*32 + d  (swapaxes(1,2) flatten)
//   out = att @ w_proj^T + b, window-scattered back to (32,56,56,256)
//
// GEMMs: R6 memory structure (cp.async fp32 double-buffer, pad-40 smem,
// conflict-free LDS.64) + fp16 mma.m16n8k16 math (cvt to half2 at fragment
// load). Half the issue slots of the tf32 version, 2x K per HMMA.
// ---------------------------------------------------------------------------

#define M_TOK 100352
#define KDIM  256
#define QKV_N 768

__device__ float g_qkv[(size_t)M_TOK * QKV_N];
__device__ float g_att[(size_t)M_TOK * KDIM];

__device__ __forceinline__ int row_offset(int n) {
    int w  = n / 49;
    int s  = n - w * 49;
    int b  = w >> 6;
    int wh = (w >> 3) & 7;
    int ww = w & 7;
    int r  = s / 7;
    int cc = s - r * 7;
    int hh = wh * 7 + r;
    int wc = ww * 7 + cc;
    return ((b * 56 + hh) * 56 + wc) * 256;
}

#define TBM 128
#define TBN 128
#define TBK 32
#define LDSP 40
#define ABUF (128 * LDSP)
#define SMEM_BYTES (4 * ABUF * 4)

__device__ __forceinline__ uint32_t pkh2(float2 v) {
    __half2 h = __floats2half2_rn(v.x, v.y);   // .x = low
    return *reinterpret_cast<uint32_t*>(&h);
}
__device__ __forceinline__ void cpa16(void* s, const void* g) {
    uint32_t sa = (uint32_t)__cvta_generic_to_shared(s);
    asm volatile("cp.async.cg.shared.global [%0], [%1], 16;" :: "r"(sa), "l"(g));
}
__device__ __forceinline__ void mma16816(float c[4], const uint32_t a[4],
                                         uint32_t b0, uint32_t b1) {
    asm volatile(
        "mma.sync.aligned.m16n8k16.row.col.f32.f16.f16.f32 "
        "{%0,%1,%2,%3}, {%4,%5,%6,%7}, {%8,%9}, {%0,%1,%2,%3};"
        : "+f"(c[0]), "+f"(c[1]), "+f"(c[2]), "+f"(c[3])
        : "r"(a[0]), "r"(a[1]), "r"(a[2]), "r"(a[3]), "r"(b0), "r"(b1));
}

template<int NTOT, bool GATHER_A, bool SCATTER_OUT>
__global__ __launch_bounds__(256)
void gemm_f16(const float* __restrict__ A, const float* __restrict__ B,
              const float* __restrict__ bias, float* __restrict__ Cout)
{
    extern __shared__ float sm[];
    float* Asm = sm;               // [2][128][40]
    float* Bsm = sm + 2 * ABUF;

    const int tid  = threadIdx.x;
    const int lane = tid & 31;
    const int warp = tid >> 5;
    const int wm = (warp & 1) * 64;
    const int wn = (warp >> 1) * 32;
    const int g  = lane >> 2;
    const int q  = lane & 3;

    const int m0 = blockIdx.y * TBM;
    const int n0 = blockIdx.x * TBN;

    const int lrow  = tid >> 1;
    const int lhalf = (tid & 1) * 16;
    const long a_base = GATHER_A ? (long)row_offset(m0 + lrow)
                                 : (long)(m0 + lrow) * KDIM;
    const long b_base = (long)(n0 + lrow) * KDIM;

    float acc[4][4][4];
    #pragma unroll
    for (int i = 0; i < 4; i++)
        #pragma unroll
        for (int j = 0; j < 4; j++)
            #pragma unroll
            for (int c = 0; c < 4; c++) acc[i][j][c] = 0.f;

    auto stage = [&](int buf, int k0) {
        float* as = Asm + buf * ABUF + lrow * LDSP + lhalf;
        float* bs = Bsm + buf * ABUF + lrow * LDSP + lhalf;
        const float* ag = A + a_base + k0 + lhalf;
        const float* bg = B + b_base + k0 + lhalf;
        #pragma unroll
        for (int i = 0; i < 4; i++) {
            cpa16(as + i * 4, ag + i * 4);
            cpa16(bs + i * 4, bg + i * 4);
        }
    };

    stage(0, 0);
    asm volatile("cp.async.commit_group;");

    const int NT = KDIM / TBK;   // 8
    #pragma unroll 1
    for (int t = 0; t < NT; ++t) {
        if (t + 1 < NT) {
            stage((t + 1) & 1, (t + 1) * TBK);
            asm volatile("cp.async.commit_group;");
            asm volatile("cp.async.wait_group 1;");
        } else {
            asm volatile("cp.async.wait_group 0;");
        }
        __syncthreads();

        const float* as = Asm + (t & 1) * ABUF;
        const float* bs = Bsm + (t & 1) * ABUF;
        #pragma unroll
        for (int kk = 0; kk < 2; kk++) {          // two k16 steps per chunk
            const int k16 = kk * 16;
            uint32_t af[4][4], bf[4][2];
            #pragma unroll
            for (int mt = 0; mt < 4; mt++) {
                const float* p = as + (wm + mt * 16 + g) * LDSP + k16 + 2 * q;
                af[mt][0] = pkh2(*(const float2*)(p));               // row g,   k 2q
                af[mt][1] = pkh2(*(const float2*)(p + 8 * LDSP));    // row g+8, k 2q
                af[mt][2] = pkh2(*(const float2*)(p + 8));           // row g,   k 2q+8
                af[mt][3] = pkh2(*(const float2*)(p + 8 * LDSP + 8));// row g+8, k 2q+8
            }
            #pragma unroll
            for (int nt = 0; nt < 4; nt++) {
                const float* p = bs + (wn + nt * 8 + g) * LDSP + k16 + 2 * q;
                bf[nt][0] = pkh2(*(const float2*)(p));
                bf[nt][1] = pkh2(*(const float2*)(p + 8));
            }
            #pragma unroll
            for (int mt = 0; mt < 4; mt++)
                #pragma unroll
                for (int nt = 0; nt < 4; nt++)
                    mma16816(acc[mt][nt], af[mt], bf[nt][0], bf[nt][1]);
        }
        __syncthreads();
    }

    // epilogue: c0,c1 = (row g, cols 2q,2q+1); c2,c3 = row g+8
    #pragma unroll
    for (int mt = 0; mt < 4; mt++) {
        #pragma unroll
        for (int ri = 0; ri < 2; ri++) {
            const int m = m0 + wm + mt * 16 + g + ri * 8;
            const long ob = SCATTER_OUT ? (long)row_offset(m) : (long)m * NTOT;
            #pragma unroll
            for (int nt = 0; nt < 4; nt++) {
                const int col = n0 + wn + nt * 8 + 2 * q;
                float2 v;
                v.x = acc[mt][nt][ri * 2 + 0];
                v.y = acc[mt][nt][ri * 2 + 1];
                if (SCATTER_OUT) {
                    v.x += bias[col];
                    v.y += bias[col + 1];
                }
                *(float2*)(Cout + ob + col) = v;
            }
        }
    }
}

// ---------------------------------------------------------------------------
// Per-token head-mixing attention (8x8 over heads), fp32.
// ---------------------------------------------------------------------------
#define ATT_TOK 14
#define ATT_THREADS (ATT_TOK * 8)

__global__ __launch_bounds__(ATT_THREADS)
void attn_kernel(const float* __restrict__ qkv, float* __restrict__ att)
{
    __shared__ float rows[ATT_TOK][776];

    const int tid  = threadIdx.x;
    const int tok0 = blockIdx.x * ATT_TOK;

    for (int i = tid; i < ATT_TOK * 192; i += ATT_THREADS) {
        int t = i / 192, c4 = (i - t * 192) * 4;
        *(float4*)&rows[t][c4] =
            *(const float4*)(qkv + (size_t)(tok0 + t) * QKV_N + c4);
    }
    __syncthreads();

    const int t = tid >> 3;
    const int h = tid & 7;
    const float* row = rows[t];

    float qv[32];
    #pragma unroll
    for (int d = 0; d < 32; d++) qv[d] = row[h * 32 + d];

    const float scale = 0.17677669529663687f;
    float a[8];
    #pragma unroll
    for (int e = 0; e < 8; e++) {
        float acc = 0.f;
        #pragma unroll
        for (int d = 0; d < 32; d++) acc += qv[d] * row[256 + e * 32 + d];
        a[e] = acc * scale;
    }

    float mx = a[0];
    #pragma unroll
    for (int e = 1; e < 8; e++) mx = fmaxf(mx, a[e]);
    float sum = 0.f;
    #pragma unroll
    for (int e = 0; e < 8; e++) { a[e] = __expf(a[e] - mx); sum += a[e]; }
    float inv = 1.f / sum;
    #pragma unroll
    for (int e = 0; e < 8; e++) a[e] *= inv;

    const int n = tok0 + t;
    const int w = n / 49;
    const int s = n - w * 49;
    float* op = att + (size_t)w * 12544 + h * 1568 + s * 32;

    #pragma unroll
    for (int d = 0; d < 32; d += 4) {
        float4 o;
        o.x = o.y = o.z = o.w = 0.f;
        #pragma unroll
        for (int e = 0; e < 8; e++) {
            const float* vp = &row[512 + e * 32 + d];
            o.x += a[e] * vp[0];
            o.y += a[e] * vp[1];
            o.z += a[e] * vp[2];
            o.w += a[e] * vp[3];
        }
        *(float4*)(op + d) = o;
    }
}

// ---------------------------------------------------------------------------
extern "C" void kernel_launch(void* const* d_in, const int* in_sizes, int n_in,
                              void* d_out, int out_size)
{
    (void)in_sizes; (void)n_in; (void)out_size;
    const float* x      = (const float*)d_in[0];
    const float* w_qkv  = (const float*)d_in[1];
    const float* w_proj = (const float*)d_in[2];
    const float* b_proj = (const float*)d_in[3];
    float* out = (float*)d_out;

    void* qkv_ptr = nullptr;
    void* att_ptr = nullptr;
    cudaGetSymbolAddress(&qkv_ptr, g_qkv);
    cudaGetSymbolAddress(&att_ptr, g_att);
    float* qkv = (float*)qkv_ptr;
    float* att = (float*)att_ptr;

    static bool attr_done = false;
    if (!attr_done) {
        cudaFuncSetAttribute(gemm_f16<QKV_N, true, false>,
                             cudaFuncAttributeMaxDynamicSharedMemorySize, SMEM_BYTES);
        cudaFuncSetAttribute(gemm_f16<KDIM, false, true>,
                             cudaFuncAttributeMaxDynamicSharedMemorySize, SMEM_BYTES);
        attr_done = true;
    }

    {
        dim3 grid(QKV_N / TBN, M_TOK / TBM);   // (6, 784)
        gemm_f16<QKV_N, true, false><<<grid, 256, SMEM_BYTES>>>(x, w_qkv, nullptr, qkv);
    }
    {
        attn_kernel<<<M_TOK / ATT_TOK, ATT_THREADS>>>(qkv, att);
    }
    {
        dim3 grid(KDIM / TBN, M_TOK / TBM);    // (2, 784)
        gemm_f16<KDIM, false, true><<<grid, 256, SMEM_BYTES>>>(att, w_proj, b_proj, out);
    }
}